// round 11
// baseline (speedup 1.0000x reference)
#include <cuda_runtime.h>
#include <mma.h>

using namespace nvcuda;

#define N_NODES 100000
#define N_EDGES 1600000
#define NE4     (N_EDGES / 4)
#define IN_DIM  128
#define HID_DIM 64
#define GB      782          // gemm tile blocks (ceil(N_NODES/128))
#define FB2     320          // fill blocks (after gemm in index order)
#define SB      98           // count+scan blocks (wave-1 resident)
#define AGG_GRID 1184        // 8 blocks/SM -> full occupancy for aggr

// ------------------------- device scratch (no allocs allowed) ---------------
// d_cnt / d_flag / d_sync* start zeroed (BSS) and are re-zeroed at the end of
// every call by the final aggregation kernel (invariant state).
__device__ int   d_cnt [N_NODES];                       // edge count per dst
__device__ int   d_fill[N_NODES];                       // fill cursors
__device__ float d_dinv[N_NODES];                       // 1/sqrt(deg) (gemm epilogue)
__device__ __align__(16) int4 d_meta[N_NODES];          // {rs, cnt, dinv_bits, 0}
__device__ int   d_csr [N_EDGES];                       // src ids bucketed by dst
__device__ __align__(16) float d_bufA[(size_t)N_NODES * HID_DIM]; // g = (A@W)*dinv
__device__ __align__(16) float d_bufB[(size_t)N_NODES * HID_DIM]; // activation
__device__ int   d_agg [SB];                            // scan block aggregates
__device__ int   d_flag[SB];                            // lookback publish flags
__device__ int   d_sync1;                               // count-done counter
__device__ int   d_sync2;                               // scan-done counter

// ------------------------- fused front kernel -------------------------------
// Roles by blockIdx.x:
//   [0, SB):        count edges -> barrier(98) -> scan -> publish scan_done
//   [SB, SB+GB):    gemm1 mainloop; spin on scan_done before dinv epilogue
//   [SB+GB, +FB2):  spin on scan_done, then CSR fill
#define SA_LD 40
#define SO_LD 68
#define SW_ELE (32 * 64)
#define SMEM_FLOATS 8704

template <int K, bool A_IS_PARAM, bool FRONT>
__global__ __launch_bounds__(256) void k_gemm_tf32(const float* __restrict__ Aparam,
                                                   const float* __restrict__ W,
                                                   const int4* __restrict__ src4,
                                                   const int4* __restrict__ dst4) {
    __shared__ __align__(16) float smem[SMEM_FLOATS];
    int tid = threadIdx.x;

    if (FRONT && blockIdx.x < SB) {
        // ---- role 1: count, barrier, scan ----
        int bid = blockIdx.x;
        for (int i = bid * 256 + tid; i < NE4; i += SB * 256) {
            int4 d = dst4[i];
            atomicAdd(&d_cnt[d.x], 1);
            atomicAdd(&d_cnt[d.y], 1);
            atomicAdd(&d_cnt[d.z], 1);
            atomicAdd(&d_cnt[d.w], 1);
        }
        __syncthreads();
        if (tid == 0) {                                 // barrier among 98 blocks
            __threadfence();
            atomicAdd(&d_sync1, 1);
            while (*((volatile int*)&d_sync1) < SB) {}
        }
        __syncthreads();

        int* sm = (int*)smem;                           // alias gemm smem
        int base = bid * 1024 + tid * 4;
        int c[4], v[4];
        int s = 0;
#pragma unroll
        for (int j = 0; j < 4; ++j) {
            int idx = base + j;
            c[j] = (idx < N_NODES) ? d_cnt[idx] : 0;
            v[j] = s; s += c[j];
        }
        sm[tid] = s;
        __syncthreads();
#pragma unroll
        for (int off = 1; off < 256; off <<= 1) {
            int t = (tid >= off) ? sm[tid - off] : 0;
            __syncthreads();
            sm[tid] += t;
            __syncthreads();
        }
        if (tid == 0) {                                 // publish block aggregate
            d_agg[bid] = sm[255];
            __threadfence();
            *((volatile int*)&d_flag[bid]) = 1;
        }
        if (tid == 255) sm[256] = 0;                    // sBase slot
        __syncthreads();
        if (tid < 32) {                                 // lookback: sum preds
            int acc = 0;
            for (int i = tid; i < bid; i += 32) {
                while (*((volatile int*)&d_flag[i]) == 0) {}
                acc += *((volatile int*)&d_agg[i]);
            }
#pragma unroll
            for (int off = 16; off; off >>= 1)
                acc += __shfl_down_sync(0xffffffffu, acc, off);
            if (tid == 0) sm[256] = acc;
        }
        __syncthreads();
        int excl = (tid == 0) ? 0 : sm[tid - 1];
        int off0 = sm[256] + excl;
#pragma unroll
        for (int j = 0; j < 4; ++j) {
            int idx = base + j;
            if (idx < N_NODES) {
                int r = off0 + v[j];
                float dv = rsqrtf((float)(c[j] + 1));
                d_fill[idx] = r;
                d_dinv[idx] = dv;
                d_meta[idx] = make_int4(r, c[j], __float_as_int(dv), 0);
            }
        }
        __syncthreads();
        if (tid == 0) {                                 // publish scan done
            __threadfence();
            atomicAdd(&d_sync2, 1);
        }
        return;
    }
    if (FRONT && blockIdx.x >= SB + GB) {
        // ---- role 3: CSR fill (after scan) ----
        if (tid == 0)
            while (*((volatile int*)&d_sync2) < SB) {}
        __syncthreads();
        int e0 = (blockIdx.x - SB - GB) * 256 + tid;
        for (int e = e0; e < NE4; e += FB2 * 256) {
            int4 d = dst4[e];
            int4 s = src4[e];
            d_csr[atomicAdd(&d_fill[d.x], 1)] = s.x;
            d_csr[atomicAdd(&d_fill[d.y], 1)] = s.y;
            d_csr[atomicAdd(&d_fill[d.z], 1)] = s.z;
            d_csr[atomicAdd(&d_fill[d.w], 1)] = s.w;
        }
        return;
    }

    // ---- role 2: TF32 GEMM, C[r,:] = (A[r,:] @ W) * dinv[r] ----
    float* sW = smem;                                   // 32 x 64
    float* sA = smem + SW_ELE;                          // 128 x SA_LD
    const float* A = A_IS_PARAM ? Aparam : (const float*)d_bufB;

    int warpId = tid >> 5;
    int r0     = (FRONT ? (blockIdx.x - SB) : blockIdx.x) * 128;
    int wrow   = warpId * 16;

    wmma::fragment<wmma::matrix_a, 16, 16, 8, wmma::precision::tf32, wmma::row_major> fa;
    wmma::fragment<wmma::matrix_b, 16, 16, 8, wmma::precision::tf32, wmma::row_major> fb;
    wmma::fragment<wmma::accumulator, 16, 16, 8, float> fc[4];
#pragma unroll
    for (int n = 0; n < 4; ++n) wmma::fill_fragment(fc[n], 0.0f);

    for (int kc = 0; kc < K; kc += 32) {
#pragma unroll
        for (int u = 0; u < 2; ++u) {                   // W chunk: 32x64
            int idx = u * 256 + tid;
            float4 v = *(const float4*)&W[(size_t)kc * 64 + idx * 4];
            *(float4*)&sW[idx * 4] = v;
        }
#pragma unroll
        for (int u = 0; u < 4; ++u) {                   // A chunk: 128x32
            int idx = u * 256 + tid;
            int row = idx >> 3;
            int c4  = idx & 7;
            int r   = r0 + row;
            float4 v = make_float4(0.f, 0.f, 0.f, 0.f);
            if (r < N_NODES)
                v = *(const float4*)&A[(size_t)r * K + kc + c4 * 4];
            *(float4*)&sA[row * SA_LD + c4 * 4] = v;
        }
        __syncthreads();
#pragma unroll
        for (int kk = 0; kk < 32; kk += 8) {
            wmma::load_matrix_sync(fa, &sA[wrow * SA_LD + kk], SA_LD);
#pragma unroll
            for (int i = 0; i < fa.num_elements; ++i)
                fa.x[i] = wmma::__float_to_tf32(fa.x[i]);
#pragma unroll
            for (int n = 0; n < 4; ++n) {
                wmma::load_matrix_sync(fb, &sW[kk * 64 + n * 16], 64);
#pragma unroll
                for (int i = 0; i < fb.num_elements; ++i)
                    fb.x[i] = wmma::__float_to_tf32(fb.x[i]);
                wmma::mma_sync(fc[n], fa, fb, fc[n]);
            }
        }
        __syncthreads();
    }

    float* sOut = smem;                                 // 128 x SO_LD
#pragma unroll
    for (int n = 0; n < 4; ++n)
        wmma::store_matrix_sync(&sOut[wrow * SO_LD + n * 16], fc[n], SO_LD,
                                wmma::mem_row_major);
    if (FRONT) {                                        // wait for dinv ready
        if (tid == 0)
            while (*((volatile int*)&d_sync2) < SB) {}
    }
    __syncthreads();
#pragma unroll
    for (int u = 0; u < 8; ++u) {
        int idx = u * 256 + tid;
        int row = idx >> 4;
        int c4  = idx & 15;
        int r   = r0 + row;
        if (r < N_NODES) {
            float s = d_dinv[r];                        // dinv fused in epilogue
            float4 v = *(float4*)&sOut[row * SO_LD + c4 * 4];
            v.x *= s; v.y *= s; v.z *= s; v.w *= s;
            *(float4*)&d_bufA[(size_t)r * 64 + c4 * 4] = v;
        }
    }
}

// ------------------------- pull aggregation ---------------------------------
// Grid-stride warp-per-node at full occupancy. Per-node metadata is ONE int4
// load {rs, cnt, dinv}, and the NEXT node's meta is prefetched before the
// gather loop so its latency hides under the gathers.
// FINAL: fuse 64->1 FC head + restore all invariant state to zero.
template <bool FINAL>
__global__ __launch_bounds__(256, 8) void k_aggr(const float* __restrict__ bias,
                                                 const float* __restrict__ Wfc,
                                                 const float* __restrict__ bfc,
                                                 float* __restrict__ outp) {
    const int NW = AGG_GRID * 8;                        // total warps
    int gw   = (blockIdx.x * blockDim.x + threadIdx.x) >> 5;
    int lane = threadIdx.x & 31;
    const float2* __restrict__ gp = (const float2*)d_bufA + lane;

    float2 bb = ((const float2*)bias)[lane];            // loop-invariant
    float2 wf;
    float  bf = 0.f;
    if (FINAL) { wf = ((const float2*)Wfc)[lane]; bf = bfc[0]; }

    int  node = gw;
    int4 m    = (node < N_NODES) ? d_meta[node] : make_int4(0, 0, 0, 0);
    for (; node < N_NODES; node += NW) {
        int nnext = node + NW;
        int4 mnext = make_int4(0, 0, 0, 0);
        if (nnext < N_NODES) mnext = d_meta[nnext];     // prefetch next meta

        int   start = m.x;
        int   cnt   = m.y;
        float di    = __int_as_float(m.z);

        float2 a0 = gp[(unsigned)node * 32u];           // self-loop term
        float2 a1 = make_float2(0.f, 0.f);
        float2 a2 = make_float2(0.f, 0.f);
        float2 a3 = make_float2(0.f, 0.f);

        int t = 0;
        for (; t + 8 <= cnt; t += 8) {                  // 8-deep MLP
            unsigned s0 = (unsigned)d_csr[start + t + 0] * 32u;
            unsigned s1 = (unsigned)d_csr[start + t + 1] * 32u;
            unsigned s2 = (unsigned)d_csr[start + t + 2] * 32u;
            unsigned s3 = (unsigned)d_csr[start + t + 3] * 32u;
            unsigned s4 = (unsigned)d_csr[start + t + 4] * 32u;
            unsigned s5 = (unsigned)d_csr[start + t + 5] * 32u;
            unsigned s6 = (unsigned)d_csr[start + t + 6] * 32u;
            unsigned s7 = (unsigned)d_csr[start + t + 7] * 32u;
            float2 v0 = gp[s0];
            float2 v1 = gp[s1];
            float2 v2 = gp[s2];
            float2 v3 = gp[s3];
            float2 v4 = gp[s4];
            float2 v5 = gp[s5];
            float2 v6 = gp[s6];
            float2 v7 = gp[s7];
            a0.x += v0.x; a0.y += v0.y;  a1.x += v1.x; a1.y += v1.y;
            a2.x += v2.x; a2.y += v2.y;  a3.x += v3.x; a3.y += v3.y;
            a0.x += v4.x; a0.y += v4.y;  a1.x += v5.x; a1.y += v5.y;
            a2.x += v6.x; a2.y += v6.y;  a3.x += v7.x; a3.y += v7.y;
        }
        for (; t < cnt; ++t) {
            float2 v = gp[(unsigned)d_csr[start + t] * 32u];
            a0.x += v.x; a0.y += v.y;
        }

        float h0 = fmaf(di, (a0.x + a1.x) + (a2.x + a3.x), bb.x);
        float h1 = fmaf(di, (a0.y + a1.y) + (a2.y + a3.y), bb.y);
        h0 = fmaxf(h0, 0.f);
        h1 = fmaxf(h1, 0.f);

        if (!FINAL) {
            *((float2*)d_bufB + lane + (unsigned)node * 32u) = make_float2(h0, h1);
        } else {
            float p = h0 * wf.x + h1 * wf.y;
#pragma unroll
            for (int off = 16; off; off >>= 1)
                p += __shfl_down_sync(0xffffffffu, p, off);
            if (lane == 0) outp[node] = p + bf;
            // restore invariant state for the next invocation
            if (lane == 1) d_cnt[node] = 0;
            if (lane == 2 && node < SB) d_flag[node] = 0;
            if (lane == 3 && node == 0) d_sync1 = 0;
            if (lane == 4 && node == 0) d_sync2 = 0;
        }
        m = mnext;
    }
}

// ------------------------- launch ------------------------------------------
extern "C" void kernel_launch(void* const* d_in, const int* in_sizes, int n_in,
                              void* d_out, int out_size) {
    const float* x    = (const float*)d_in[0];
    const int*   ei   = (const int*)d_in[1];   // JAX x64 disabled: int32
    const float* W1   = (const float*)d_in[2];
    const float* b1   = (const float*)d_in[3];
    const float* W2   = (const float*)d_in[4];
    const float* b2   = (const float*)d_in[5];
    const float* Wfc  = (const float*)d_in[6];
    const float* bfc  = (const float*)d_in[7];
    float*       out  = (float*)d_out;

    const int4* src4 = (const int4*)ei;                 // edge_index[0]
    const int4* dst4 = (const int4*)(ei + N_EDGES);     // edge_index[1]

    // fused front: count+scan (blocks 0..97) || gemm1 (98..879) || fill (880..)
    k_gemm_tf32<IN_DIM, true, true ><<<SB + GB + FB2, 256>>>(x, W1, src4, dst4);
    k_aggr<false><<<AGG_GRID, 256>>>(b1, Wfc, bfc, out);
    // layer 2 + fused FC head (+ state restore)
    k_gemm_tf32<HID_DIM, false, false><<<GB, 256>>>(x /*unused*/, W2, nullptr, nullptr);
    k_aggr<true ><<<AGG_GRID, 256>>>(b2, Wfc, bfc, out);
}

// round 12
// speedup vs baseline: 1.0622x; 1.0622x over previous
#include <cuda_runtime.h>
#include <mma.h>

using namespace nvcuda;

#define N_NODES 100000
#define N_EDGES 1600000
#define NE4     (N_EDGES / 4)
#define IN_DIM  128
#define HID_DIM 64
#define GB      782          // gemm tile blocks (ceil(N_NODES/128))
#define FB2     320          // fill blocks (after gemm in index order)
#define SB      98           // count+scan blocks (wave-1 resident)
#define AGG_GRID 1184        // 8 blocks/SM -> full occupancy for aggr

// ------------------------- device scratch (no allocs allowed) ---------------
// d_cnt / d_flag / d_sync* start zeroed (BSS) and are re-zeroed at the end of
// every call by the final aggregation kernel (invariant state).
__device__ int   d_cnt [N_NODES];                       // edge count per dst
__device__ int   d_rs  [N_NODES];                       // CSR row starts
__device__ int   d_fill[N_NODES];                       // fill cursors
__device__ float d_dinv[N_NODES];                       // 1/sqrt(deg) (deg=cnt+1)
__device__ __align__(16) int d_csr[N_EDGES];            // src ids bucketed by dst
__device__ __align__(16) float d_bufA[(size_t)N_NODES * HID_DIM]; // g = (A@W)*dinv
__device__ __align__(16) float d_bufB[(size_t)N_NODES * HID_DIM]; // activation
__device__ int   d_agg [SB];                            // scan block aggregates
__device__ int   d_flag[SB];                            // lookback publish flags
__device__ int   d_sync1;                               // count-done counter
__device__ int   d_sync2;                               // scan-done counter

// ------------------------- fused front kernel -------------------------------
// Roles by blockIdx.x:
//   [0, SB):        count edges -> barrier(98) -> scan -> publish scan_done
//   [SB, SB+GB):    gemm1 mainloop; spin on scan_done before dinv epilogue
//   [SB+GB, +FB2):  spin on scan_done, then CSR fill
#define SA_LD 40
#define SO_LD 68
#define SW_ELE (32 * 64)
#define SMEM_FLOATS 8704

template <int K, bool A_IS_PARAM, bool FRONT>
__global__ __launch_bounds__(256) void k_gemm_tf32(const float* __restrict__ Aparam,
                                                   const float* __restrict__ W,
                                                   const int4* __restrict__ src4,
                                                   const int4* __restrict__ dst4) {
    __shared__ __align__(16) float smem[SMEM_FLOATS];
    int tid = threadIdx.x;

    if (FRONT && blockIdx.x < SB) {
        // ---- role 1: count, barrier, scan ----
        int bid = blockIdx.x;
        for (int i = bid * 256 + tid; i < NE4; i += SB * 256) {
            int4 d = dst4[i];
            atomicAdd(&d_cnt[d.x], 1);
            atomicAdd(&d_cnt[d.y], 1);
            atomicAdd(&d_cnt[d.z], 1);
            atomicAdd(&d_cnt[d.w], 1);
        }
        __syncthreads();
        if (tid == 0) {                                 // barrier among 98 blocks
            __threadfence();
            atomicAdd(&d_sync1, 1);
            while (*((volatile int*)&d_sync1) < SB) {}
        }
        __syncthreads();

        int* sm = (int*)smem;                           // alias gemm smem
        int base = bid * 1024 + tid * 4;
        int c[4], v[4];
        int s = 0;
#pragma unroll
        for (int j = 0; j < 4; ++j) {
            int idx = base + j;
            c[j] = (idx < N_NODES) ? d_cnt[idx] : 0;
            v[j] = s; s += c[j];
        }
        sm[tid] = s;
        __syncthreads();
#pragma unroll
        for (int off = 1; off < 256; off <<= 1) {
            int t = (tid >= off) ? sm[tid - off] : 0;
            __syncthreads();
            sm[tid] += t;
            __syncthreads();
        }
        if (tid == 0) {                                 // publish block aggregate
            d_agg[bid] = sm[255];
            __threadfence();
            *((volatile int*)&d_flag[bid]) = 1;
        }
        if (tid == 255) sm[256] = 0;                    // sBase slot
        __syncthreads();
        if (tid < 32) {                                 // lookback: sum preds
            int acc = 0;
            for (int i = tid; i < bid; i += 32) {
                while (*((volatile int*)&d_flag[i]) == 0) {}
                acc += *((volatile int*)&d_agg[i]);
            }
#pragma unroll
            for (int off = 16; off; off >>= 1)
                acc += __shfl_down_sync(0xffffffffu, acc, off);
            if (tid == 0) sm[256] = acc;
        }
        __syncthreads();
        int excl = (tid == 0) ? 0 : sm[tid - 1];
        int off0 = sm[256] + excl;
#pragma unroll
        for (int j = 0; j < 4; ++j) {
            int idx = base + j;
            if (idx < N_NODES) {
                int r = off0 + v[j];
                d_rs[idx]   = r;
                d_fill[idx] = r;
                d_dinv[idx] = rsqrtf((float)(c[j] + 1));
            }
        }
        __syncthreads();
        if (tid == 0) {                                 // publish scan done
            __threadfence();
            atomicAdd(&d_sync2, 1);
        }
        return;
    }
    if (FRONT && blockIdx.x >= SB + GB) {
        // ---- role 3: CSR fill (after scan) ----
        if (tid == 0)
            while (*((volatile int*)&d_sync2) < SB) {}
        __syncthreads();
        int e0 = (blockIdx.x - SB - GB) * 256 + tid;
        for (int e = e0; e < NE4; e += FB2 * 256) {
            int4 d = dst4[e];
            int4 s = src4[e];
            d_csr[atomicAdd(&d_fill[d.x], 1)] = s.x;
            d_csr[atomicAdd(&d_fill[d.y], 1)] = s.y;
            d_csr[atomicAdd(&d_fill[d.z], 1)] = s.z;
            d_csr[atomicAdd(&d_fill[d.w], 1)] = s.w;
        }
        return;
    }

    // ---- role 2: TF32 GEMM, C[r,:] = (A[r,:] @ W) * dinv[r] ----
    float* sW = smem;                                   // 32 x 64
    float* sA = smem + SW_ELE;                          // 128 x SA_LD
    const float* A = A_IS_PARAM ? Aparam : (const float*)d_bufB;

    int warpId = tid >> 5;
    int r0     = (FRONT ? (blockIdx.x - SB) : blockIdx.x) * 128;
    int wrow   = warpId * 16;

    wmma::fragment<wmma::matrix_a, 16, 16, 8, wmma::precision::tf32, wmma::row_major> fa;
    wmma::fragment<wmma::matrix_b, 16, 16, 8, wmma::precision::tf32, wmma::row_major> fb;
    wmma::fragment<wmma::accumulator, 16, 16, 8, float> fc[4];
#pragma unroll
    for (int n = 0; n < 4; ++n) wmma::fill_fragment(fc[n], 0.0f);

    for (int kc = 0; kc < K; kc += 32) {
#pragma unroll
        for (int u = 0; u < 2; ++u) {                   // W chunk: 32x64
            int idx = u * 256 + tid;
            float4 v = *(const float4*)&W[(size_t)kc * 64 + idx * 4];
            *(float4*)&sW[idx * 4] = v;
        }
#pragma unroll
        for (int u = 0; u < 4; ++u) {                   // A chunk: 128x32
            int idx = u * 256 + tid;
            int row = idx >> 3;
            int c4  = idx & 7;
            int r   = r0 + row;
            float4 v = make_float4(0.f, 0.f, 0.f, 0.f);
            if (r < N_NODES)
                v = *(const float4*)&A[(size_t)r * K + kc + c4 * 4];
            *(float4*)&sA[row * SA_LD + c4 * 4] = v;
        }
        __syncthreads();
#pragma unroll
        for (int kk = 0; kk < 32; kk += 8) {
            wmma::load_matrix_sync(fa, &sA[wrow * SA_LD + kk], SA_LD);
#pragma unroll
            for (int i = 0; i < fa.num_elements; ++i)
                fa.x[i] = wmma::__float_to_tf32(fa.x[i]);
#pragma unroll
            for (int n = 0; n < 4; ++n) {
                wmma::load_matrix_sync(fb, &sW[kk * 64 + n * 16], 64);
#pragma unroll
                for (int i = 0; i < fb.num_elements; ++i)
                    fb.x[i] = wmma::__float_to_tf32(fb.x[i]);
                wmma::mma_sync(fc[n], fa, fb, fc[n]);
            }
        }
        __syncthreads();
    }

    float* sOut = smem;                                 // 128 x SO_LD
#pragma unroll
    for (int n = 0; n < 4; ++n)
        wmma::store_matrix_sync(&sOut[wrow * SO_LD + n * 16], fc[n], SO_LD,
                                wmma::mem_row_major);
    if (FRONT) {                                        // wait for dinv ready
        if (tid == 0)
            while (*((volatile int*)&d_sync2) < SB) {}
    }
    __syncthreads();
#pragma unroll
    for (int u = 0; u < 8; ++u) {
        int idx = u * 256 + tid;
        int row = idx >> 4;
        int c4  = idx & 15;
        int r   = r0 + row;
        if (r < N_NODES) {
            float s = d_dinv[r];                        // dinv fused in epilogue
            float4 v = *(float4*)&sOut[row * SO_LD + c4 * 4];
            v.x *= s; v.y *= s; v.z *= s; v.w *= s;
            *(float4*)&d_bufA[(size_t)r * 64 + c4 * 4] = v;
        }
    }
}

// ------------------------- pull aggregation ---------------------------------
// Grid-stride warp-per-node at full occupancy. CSR index stream loaded as
// int4 pairs (after scalar peel to 16B alignment): 8 index LDGs -> 2, less
// issue pressure + earlier gather addresses.
// FINAL: fuse 64->1 FC head + restore all invariant state to zero.
template <bool FINAL>
__global__ __launch_bounds__(256, 8) void k_aggr(const float* __restrict__ bias,
                                                 const float* __restrict__ Wfc,
                                                 const float* __restrict__ bfc,
                                                 float* __restrict__ outp) {
    const int NW = AGG_GRID * 8;                        // total warps
    int gw   = (blockIdx.x * blockDim.x + threadIdx.x) >> 5;
    int lane = threadIdx.x & 31;
    const float2* __restrict__ gp = (const float2*)d_bufA + lane;

    float2 bb = ((const float2*)bias)[lane];            // loop-invariant
    float2 wf;
    float  bf = 0.f;
    if (FINAL) { wf = ((const float2*)Wfc)[lane]; bf = bfc[0]; }

    for (int node = gw; node < N_NODES; node += NW) {
        int start = d_rs[node];
        int cnt   = d_cnt[node];

        float2 a0 = gp[(unsigned)node * 32u];           // self-loop term
        float2 a1 = make_float2(0.f, 0.f);
        float2 a2 = make_float2(0.f, 0.f);
        float2 a3 = make_float2(0.f, 0.f);

        // scalar peel until (start + t) is 16B aligned
        int t = 0;
        int pre = (4 - (start & 3)) & 3;
        if (pre > cnt) pre = cnt;
        for (; t < pre; ++t) {
            float2 v = gp[(unsigned)d_csr[start + t] * 32u];
            a0.x += v.x; a0.y += v.y;
        }
        const int4* __restrict__ cp = (const int4*)(d_csr + start + t);
        for (; t + 8 <= cnt; t += 8, cp += 2) {         // 2 int4 index loads
            int4 ia = cp[0];
            int4 ib = cp[1];
            float2 v0 = gp[(unsigned)ia.x * 32u];
            float2 v1 = gp[(unsigned)ia.y * 32u];
            float2 v2 = gp[(unsigned)ia.z * 32u];
            float2 v3 = gp[(unsigned)ia.w * 32u];
            float2 v4 = gp[(unsigned)ib.x * 32u];
            float2 v5 = gp[(unsigned)ib.y * 32u];
            float2 v6 = gp[(unsigned)ib.z * 32u];
            float2 v7 = gp[(unsigned)ib.w * 32u];
            a0.x += v0.x; a0.y += v0.y;  a1.x += v1.x; a1.y += v1.y;
            a2.x += v2.x; a2.y += v2.y;  a3.x += v3.x; a3.y += v3.y;
            a0.x += v4.x; a0.y += v4.y;  a1.x += v5.x; a1.y += v5.y;
            a2.x += v6.x; a2.y += v6.y;  a3.x += v7.x; a3.y += v7.y;
        }
        for (; t < cnt; ++t) {
            float2 v = gp[(unsigned)d_csr[start + t] * 32u];
            a0.x += v.x; a0.y += v.y;
        }

        float di = d_dinv[node];
        float h0 = fmaf(di, (a0.x + a1.x) + (a2.x + a3.x), bb.x);
        float h1 = fmaf(di, (a0.y + a1.y) + (a2.y + a3.y), bb.y);
        h0 = fmaxf(h0, 0.f);
        h1 = fmaxf(h1, 0.f);

        if (!FINAL) {
            *((float2*)d_bufB + lane + (unsigned)node * 32u) = make_float2(h0, h1);
        } else {
            float p = h0 * wf.x + h1 * wf.y;
#pragma unroll
            for (int off = 16; off; off >>= 1)
                p += __shfl_down_sync(0xffffffffu, p, off);
            if (lane == 0) outp[node] = p + bf;
            // restore invariant state for the next invocation
            if (lane == 1) d_cnt[node] = 0;
            if (lane == 2 && node < SB) d_flag[node] = 0;
            if (lane == 3 && node == 0) d_sync1 = 0;
            if (lane == 4 && node == 0) d_sync2 = 0;
        }
    }
}

// ------------------------- launch ------------------------------------------
extern "C" void kernel_launch(void* const* d_in, const int* in_sizes, int n_in,
                              void* d_out, int out_size) {
    const float* x    = (const float*)d_in[0];
    const int*   ei   = (const int*)d_in[1];   // JAX x64 disabled: int32
    const float* W1   = (const float*)d_in[2];
    const float* b1   = (const float*)d_in[3];
    const float* W2   = (const float*)d_in[4];
    const float* b2   = (const float*)d_in[5];
    const float* Wfc  = (const float*)d_in[6];
    const float* bfc  = (const float*)d_in[7];
    float*       out  = (float*)d_out;

    const int4* src4 = (const int4*)ei;                 // edge_index[0]
    const int4* dst4 = (const int4*)(ei + N_EDGES);     // edge_index[1]

    // fused front: count+scan (blocks 0..97) || gemm1 (98..879) || fill (880..)
    k_gemm_tf32<IN_DIM, true, true ><<<SB + GB + FB2, 256>>>(x, W1, src4, dst4);
    k_aggr<false><<<AGG_GRID, 256>>>(b1, Wfc, bfc, out);
    // layer 2 + fused FC head (+ state restore)
    k_gemm_tf32<HID_DIM, false, false><<<GB, 256>>>(x /*unused*/, W2, nullptr, nullptr);
    k_aggr<true ><<<AGG_GRID, 256>>>(b2, Wfc, bfc, out);
}